// round 6
// baseline (speedup 1.0000x reference)
#include <cuda_runtime.h>
#include <cuda_bf16.h>
#include <cstdint>
#include <math.h>

#define Bn 32
#define Ln 1024
#define En 512
#define Mn 64

// ---------------- scratch (static device globals; no runtime alloc) ----------
__device__ float g_X[Bn * 128 * En];                           // [b][r][h]
__device__ float g_Z[Bn * 128 * En];                           // [b][k][i]
__device__ float g_Wtr[Mn * En * En];                          // [m][h][i]
__device__ float g_Wti[Mn * En * En];
__device__ __align__(16) __nv_bfloat16 g_qTh[Bn * En * Ln];    // [b][h][l]
__device__ __align__(16) __nv_bfloat16 g_qTl[Bn * En * Ln];
__device__ __align__(16) __nv_bfloat16 g_Zth[Bn * En * 128];   // [b][i][k]
__device__ __align__(16) __nv_bfloat16 g_Ztl[Bn * En * 128];
__device__ __align__(16) __nv_bfloat16 g_t1h[128 * Ln];        // [r][l]
__device__ __align__(16) __nv_bfloat16 g_t1l[128 * Ln];
__device__ __align__(16) __nv_bfloat16 g_t3h[Ln * 128];        // [l][k]
__device__ __align__(16) __nv_bfloat16 g_t3l[Ln * 128];

__device__ __forceinline__ void bsplit(float v, __nv_bfloat16& h, __nv_bfloat16& l) {
    h = __float2bfloat16(v);
    l = __float2bfloat16(v - __bfloat162float(h));
}

__device__ __forceinline__ uint32_t smem_u32(const void* p) {
    uint32_t a;
    asm("{ .reg .u64 t; cvta.to.shared.u64 t, %1; cvt.u32.u64 %0, t; }" : "=r"(a) : "l"(p));
    return a;
}

// ---------------- trig tables (bf16 split) -----------------------------------
__global__ void trig1_kernel() {
    int idx = blockIdx.x * 256 + threadIdx.x;     // 128*1024
    int r = idx >> 10, l = idx & 1023;
    int m = r & 63;
    float s, c;
    sincospif((float)((l * m) & 1023) * (1.0f / 512.0f), &s, &c);
    float v = (r < 64) ? c : -s;
    bsplit(v, g_t1h[idx], g_t1l[idx]);
}
__global__ void trig3_kernel() {
    int idx = blockIdx.x * 256 + threadIdx.x;     // 1024*128
    int l = idx >> 7, k = idx & 127;
    int m = k >> 1;
    float s, c;
    sincospif((float)((l * m) & 1023) * (1.0f / 512.0f), &s, &c);
    float v = (k & 1) ? -s : c;
    bsplit(v, g_t3h[idx], g_t3l[idx]);
}

// ---------------- W transpose: W[h][i][m] -> Wt[m][h][i] ----------------------
__global__ __launch_bounds__(256) void wtrans_kernel(const float* __restrict__ wr,
                                                     const float* __restrict__ wi) {
    __shared__ float tile[64][33];
    const float* src = blockIdx.z ? wi : wr;
    float* dst = blockIdx.z ? g_Wti : g_Wtr;
    int h = blockIdx.y;
    int i0 = blockIdx.x * 32;
    int tid = threadIdx.x;
    #pragma unroll
    for (int e0 = 0; e0 < 8; e0++) {
        int e = tid + e0 * 256;
        int ii = e >> 6, m = e & 63;
        tile[m][ii] = src[((size_t)h * En + (size_t)(i0 + ii)) * Mn + m];
    }
    __syncthreads();
    #pragma unroll
    for (int e0 = 0; e0 < 8; e0++) {
        int e = tid + e0 * 256;
        int m = e >> 5, ii = e & 31;
        dst[((size_t)m * En + h) * En + i0 + ii] = tile[m][ii];
    }
}

// ---------------- q transpose + bf16 split: q[b][l][h] -> qT[b][h][l] ---------
__global__ __launch_bounds__(256) void qsplit_kernel(const float* __restrict__ q) {
    __shared__ float sm[64][65];
    int h0 = blockIdx.x * 64, l0 = blockIdx.y * 64, b = blockIdx.z;
    int tid = threadIdx.x;
    #pragma unroll
    for (int i = 0; i < 16; i++) {
        int e = tid + i * 256;
        int lr = e >> 6, hc = e & 63;
        sm[lr][hc] = q[((size_t)(b * Ln + l0 + lr)) * En + h0 + hc];
    }
    __syncthreads();
    #pragma unroll
    for (int i = 0; i < 16; i++) {
        int e = tid + i * 256;
        int hr = e >> 6, lc = e & 63;
        float v = sm[lc][hr];
        size_t o = ((size_t)(b * En + h0 + hr)) * Ln + l0 + lc;
        bsplit(v, g_qTh[o], g_qTl[o]);
    }
}

// ---------------- Z transpose + split: Z[b][k][i] -> Zt[b][i][k] --------------
__global__ __launch_bounds__(256) void ztrans_kernel() {
    __shared__ float sm[128][65];
    int i0 = blockIdx.x * 64, b = blockIdx.y;
    int tid = threadIdx.x;
    const float* Zb = g_Z + (size_t)b * 128 * En;
    #pragma unroll
    for (int i = 0; i < 32; i++) {
        int e = tid + i * 256;
        int kr = e >> 6, ic = e & 63;
        sm[kr][ic] = Zb[(size_t)kr * En + i0 + ic];
    }
    __syncthreads();
    #pragma unroll
    for (int i = 0; i < 32; i++) {
        int e = tid + i * 256;
        int ir = e >> 7, kc = e & 127;
        float v = sm[kc][ir];
        size_t o = ((size_t)(b * En + i0 + ir)) * 128 + kc;
        bsplit(v, g_Zth[o], g_Ztl[o]);
    }
}

// ---------------- mma.sync GEMM machinery -------------------------------------
// smem tile: 128 rows x 64 bf16 cols, stored as 16B groups with XOR swizzle:
// byte_off(row, c8) = (row*8 + (c8 ^ (row & 7))) * 16
__device__ __forceinline__ void load_chunk(char* dst, const __nv_bfloat16* __restrict__ src,
                                           int stride, int tid) {
    #pragma unroll
    for (int i = 0; i < 4; i++) {
        int g = tid + i * 256;
        int row = g >> 3, c8 = g & 7;
        uint32_t off = (uint32_t)((row << 3) + (c8 ^ (row & 7))) << 4;
        *(uint4*)(dst + off) = *(const uint4*)(src + (size_t)row * stride + c8 * 8);
    }
}

__device__ __forceinline__ void ldsm_x4(uint32_t* r, uint32_t addr) {
    asm volatile("ldmatrix.sync.aligned.m8n8.x4.shared.b16 {%0,%1,%2,%3}, [%4];"
                 : "=r"(r[0]), "=r"(r[1]), "=r"(r[2]), "=r"(r[3]) : "r"(addr));
}
__device__ __forceinline__ void ldsm_x2(uint32_t* r, uint32_t addr) {
    asm volatile("ldmatrix.sync.aligned.m8n8.x2.shared.b16 {%0,%1}, [%2];"
                 : "=r"(r[0]), "=r"(r[1]) : "r"(addr));
}
__device__ __forceinline__ void mma_bf16(float* c, const uint32_t* a, const uint32_t* b) {
    asm volatile(
        "mma.sync.aligned.m16n8k16.row.col.f32.bf16.bf16.f32 "
        "{%0,%1,%2,%3}, {%4,%5,%6,%7}, {%8,%9}, {%0,%1,%2,%3};"
        : "+f"(c[0]), "+f"(c[1]), "+f"(c[2]), "+f"(c[3])
        : "r"(a[0]), "r"(a[1]), "r"(a[2]), "r"(a[3]), "r"(b[0]), "r"(b[1]));
}

// one 64-wide K-chunk: warp tile 64x32 (wm x wn), c[mi][ni][4]
__device__ __forceinline__ void mma_chunk(uint32_t sA, uint32_t sB, int lane,
                                          int wm, int wn, float c[4][4][4]) {
    #pragma unroll
    for (int kk = 0; kk < 4; kk++) {
        uint32_t a[4][4], bf[4][2];
        int arow = wm + (lane & 15);
        int ac8 = kk * 2 + (lane >> 4);
        #pragma unroll
        for (int mi = 0; mi < 4; mi++) {
            int row = arow + mi * 16;
            uint32_t off = (uint32_t)((row << 3) + (ac8 ^ (row & 7))) << 4;
            ldsm_x4(a[mi], sA + off);
        }
        int brow = wn + (lane & 7);
        int bc8 = kk * 2 + ((lane >> 3) & 1);
        #pragma unroll
        for (int ni = 0; ni < 4; ni++) {
            int row = brow + ni * 8;
            uint32_t off = (uint32_t)((row << 3) + (bc8 ^ (row & 7))) << 4;
            ldsm_x2(bf[ni], sB + off);
        }
        #pragma unroll
        for (int mi = 0; mi < 4; mi++)
            #pragma unroll
            for (int ni = 0; ni < 4; ni++)
                mma_bf16(c[mi][ni], a[mi], bf[ni]);
    }
}

#define GEMM_SMEM 65536   // A0,A1,B0,B1 @ 16KB each

// ---------------- stage 1 (mma): X[b][r][h] = trig1 * qT^T --------------------
__global__ __launch_bounds__(256) void s1_kernel() {
    extern __shared__ char smem[];
    uint32_t sbase = smem_u32(smem);
    int tid = threadIdx.x, wid = tid >> 5, lane = tid & 31;
    int h0 = blockIdx.x * 128, b = blockIdx.y;
    int wm = (wid >> 2) * 64, wn = (wid & 3) * 32;

    const __nv_bfloat16* Aseg[3] = {g_t1h, g_t1l, g_t1h};
    const __nv_bfloat16* Bseg[3] = {g_qTh, g_qTh, g_qTl};
    const size_t bOff = ((size_t)(b * En + h0)) * Ln;

    float c[4][4][4] = {};
    char* bufA[2] = {smem, smem + 16384};
    char* bufB[2] = {smem + 32768, smem + 49152};

    load_chunk(bufA[0], Aseg[0], Ln, tid);
    load_chunk(bufB[0], Bseg[0] + bOff, Ln, tid);
    __syncthreads();

    for (int ch = 0; ch < 48; ch++) {
        int p = ch & 1;
        if (ch + 1 < 48) {
            int cn = ch + 1, seg = cn >> 4, k0 = (cn & 15) * 64;
            load_chunk(bufA[1 - p], Aseg[seg] + k0, Ln, tid);
            load_chunk(bufB[1 - p], Bseg[seg] + bOff + k0, Ln, tid);
        }
        mma_chunk(sbase + (uint32_t)(p * 16384), sbase + 32768u + (uint32_t)(p * 16384),
                  lane, wm, wn, c);
        __syncthreads();
    }

    float* dst = g_X + (size_t)b * 128 * En + h0;
    #pragma unroll
    for (int mi = 0; mi < 4; mi++)
        #pragma unroll
        for (int ni = 0; ni < 4; ni++) {
            int r = wm + mi * 16 + (lane >> 2);
            int col = wn + ni * 8 + (lane & 3) * 2;
            *(float2*)(dst + (size_t)r * En + col) = make_float2(c[mi][ni][0], c[mi][ni][1]);
            *(float2*)(dst + (size_t)(r + 8) * En + col) = make_float2(c[mi][ni][2], c[mi][ni][3]);
        }
}

// ---------------- stage 2: per-mode complex GEMM (scalar) ---------------------
__global__ __launch_bounds__(256) void modegemm_kernel() {
    __shared__ float sAr[32][34], sAi[32][34];
    __shared__ float sBr[32][68], sBi[32][68];

    int tid = threadIdx.x;
    int m = blockIdx.y;
    int i0 = blockIdx.x * 64;
    int ty = tid >> 4, tx = tid & 15;

    float accr[2][4] = {}, acci[2][4] = {};

    const float* Xr = g_X + (size_t)m * En;
    const float* Xi = g_X + (size_t)(Mn + m) * En;
    const float* Wr = g_Wtr + (size_t)m * En * En;
    const float* Wi = g_Wti + (size_t)m * En * En;

    for (int h0 = 0; h0 < En; h0 += 32) {
        #pragma unroll
        for (int e0 = 0; e0 < 4; e0++) {
            int e = tid + e0 * 256;
            int bb = e >> 5, k = e & 31;
            size_t off = (size_t)bb * 128 * En + h0 + k;
            sAr[k][bb] = Xr[off];
            sAi[k][bb] = Xi[off];
        }
        #pragma unroll
        for (int e0 = 0; e0 < 8; e0++) {
            int e = tid + e0 * 256;
            int k = e >> 6, j = e & 63;
            size_t off = (size_t)(h0 + k) * En + i0 + j;
            sBr[k][j] = Wr[off];
            sBi[k][j] = Wi[off];
        }
        __syncthreads();
        #pragma unroll
        for (int k = 0; k < 32; k++) {
            float2 arv = *(const float2*)&sAr[k][ty * 2];
            float2 aiv = *(const float2*)&sAi[k][ty * 2];
            float4 brv = *(const float4*)&sBr[k][tx * 4];
            float4 biv = *(const float4*)&sBi[k][tx * 4];
            float ar[2] = {arv.x, arv.y};
            float ai[2] = {aiv.x, aiv.y};
            float br[4] = {brv.x, brv.y, brv.z, brv.w};
            float bi[4] = {biv.x, biv.y, biv.z, biv.w};
            #pragma unroll
            for (int u = 0; u < 2; u++)
                #pragma unroll
                for (int v = 0; v < 4; v++) {
                    accr[u][v] += ar[u] * br[v];
                    accr[u][v] -= ai[u] * bi[v];
                    acci[u][v] += ar[u] * bi[v];
                    acci[u][v] += ai[u] * br[v];
                }
        }
        __syncthreads();
    }

    float w = (m == 0 ? 1.0f : 2.0f) / (float)Ln;
    #pragma unroll
    for (int u = 0; u < 2; u++) {
        int bb = ty * 2 + u;
        float* Zb = g_Z + ((size_t)bb * 128 + 2 * m) * En + i0 + tx * 4;
        float4 zr = make_float4(w * accr[u][0], w * accr[u][1], w * accr[u][2], w * accr[u][3]);
        float4 zi = make_float4(w * acci[u][0], w * acci[u][1], w * acci[u][2], w * acci[u][3]);
        *(float4*)Zb = zr;
        *(float4*)(Zb + En) = zi;
    }
}

// ---------------- stage 3 (mma): out[b][l][i] = trig3 * Zt^T ------------------
__global__ __launch_bounds__(256) void s3_kernel(float* __restrict__ out) {
    extern __shared__ char smem[];
    uint32_t sbase = smem_u32(smem);
    int tid = threadIdx.x, wid = tid >> 5, lane = tid & 31;
    int i0 = blockIdx.x * 128, l0 = blockIdx.y * 128, b = blockIdx.z;
    int wm = (wid >> 2) * 64, wn = (wid & 3) * 32;

    const __nv_bfloat16* Aseg[3] = {g_t3h, g_t3l, g_t3h};
    const __nv_bfloat16* Bseg[3] = {g_Zth, g_Zth, g_Ztl};
    const size_t aOff = (size_t)l0 * 128;
    const size_t bOff = ((size_t)(b * En + i0)) * 128;

    float c[4][4][4] = {};
    char* bufA[2] = {smem, smem + 16384};
    char* bufB[2] = {smem + 32768, smem + 49152};

    load_chunk(bufA[0], Aseg[0] + aOff, 128, tid);
    load_chunk(bufB[0], Bseg[0] + bOff, 128, tid);
    __syncthreads();

    for (int ch = 0; ch < 6; ch++) {
        int p = ch & 1;
        if (ch + 1 < 6) {
            int cn = ch + 1, seg = cn >> 1, k0 = (cn & 1) * 64;
            load_chunk(bufA[1 - p], Aseg[seg] + aOff + k0, 128, tid);
            load_chunk(bufB[1 - p], Bseg[seg] + bOff + k0, 128, tid);
        }
        mma_chunk(sbase + (uint32_t)(p * 16384), sbase + 32768u + (uint32_t)(p * 16384),
                  lane, wm, wn, c);
        __syncthreads();
    }

    float* dst = out + ((size_t)(b * Ln + l0)) * En + i0;
    #pragma unroll
    for (int mi = 0; mi < 4; mi++)
        #pragma unroll
        for (int ni = 0; ni < 4; ni++) {
            int r = wm + mi * 16 + (lane >> 2);
            int col = wn + ni * 8 + (lane & 3) * 2;
            *(float2*)(dst + (size_t)r * En + col) = make_float2(c[mi][ni][0], c[mi][ni][1]);
            *(float2*)(dst + (size_t)(r + 8) * En + col) = make_float2(c[mi][ni][2], c[mi][ni][3]);
        }
}

// ---------------- launch ------------------------------------------------------
extern "C" void kernel_launch(void* const* d_in, const int* in_sizes, int n_in,
                              void* d_out, int out_size) {
    (void)in_sizes; (void)n_in; (void)out_size;
    const float* q  = (const float*)d_in[0];
    const float* wr = (const float*)d_in[1];
    const float* wi = (const float*)d_in[2];
    float* out = (float*)d_out;

    cudaFuncSetAttribute(s1_kernel, cudaFuncAttributeMaxDynamicSharedMemorySize, GEMM_SMEM);
    cudaFuncSetAttribute(s3_kernel, cudaFuncAttributeMaxDynamicSharedMemorySize, GEMM_SMEM);

    trig1_kernel<<<512, 256>>>();
    trig3_kernel<<<512, 256>>>();
    wtrans_kernel<<<dim3(16, 512, 2), 256>>>(wr, wi);
    qsplit_kernel<<<dim3(8, 16, 32), 256>>>(q);
    s1_kernel<<<dim3(4, 32), 256, GEMM_SMEM>>>();
    modegemm_kernel<<<dim3(8, 64), 256>>>();
    ztrans_kernel<<<dim3(8, 32), 256>>>();
    s3_kernel<<<dim3(4, 8, 32), 256, GEMM_SMEM>>>(out);
}